// round 8
// baseline (speedup 1.0000x reference)
#include <cuda_runtime.h>
#include <math.h>

#define B_    128
#define T_    256
#define IN_   256
#define HID_  512
#define NG_   1536   // 3*HID
#define OUT_  64

// ---------------- scratch (static __device__, no allocation) ----------------
__device__ float g_xg[(size_t)B_ * T_ * NG_];
__device__ float g_h0[(size_t)B_ * T_ * HID_];
__device__ float g_h1[(size_t)B_ * T_ * HID_];
__device__ unsigned g_ctr[2];

// ---------------- packed f32x2 helpers --------------------------------------
__device__ __forceinline__ unsigned long long fma2(unsigned long long a,
                                                   unsigned long long b,
                                                   unsigned long long c) {
    unsigned long long d;
    asm("fma.rn.f32x2 %0, %1, %2, %3;" : "=l"(d) : "l"(a), "l"(b), "l"(c));
    return d;
}
__device__ __forceinline__ unsigned long long add2(unsigned long long a,
                                                   unsigned long long b) {
    unsigned long long d;
    asm("add.rn.f32x2 %0, %1, %2;" : "=l"(d) : "l"(a), "l"(b));
    return d;
}
__device__ __forceinline__ void unpack2(unsigned long long v, float& x, float& y) {
    asm("mov.b64 {%0, %1}, %2;" : "=f"(x), "=f"(y) : "l"(v));
}
__device__ __forceinline__ unsigned f2tf32(float f) {
    unsigned u;
    asm("cvt.rna.tf32.f32 %0, %1;" : "=r"(u) : "f"(f));
    return u;
}

// ============================================================================
// tf32 tensor-core GEMM: out[M,N] = X[M,K] @ W[N,K]^T + bias[N]
// 128x128x32 tile, 256 threads = 8 warps (4m x 2n), warp tile 32x64.
// ============================================================================
#define BM 128
#define BN 128
#define BK 32
#define SP 36

__global__ __launch_bounds__(256, 2)
void gemm_tf32(const float* __restrict__ X, const float* __restrict__ W,
               const float* __restrict__ bias, float* __restrict__ out,
               int M, int N, int K)
{
    __shared__ unsigned Xs[BM][SP];
    __shared__ unsigned Ws[BN][SP];

    const int tid  = threadIdx.x;
    const int lane = tid & 31;
    const int wid  = tid >> 5;
    const int g    = lane >> 2;
    const int tg   = lane & 3;
    const int wm   = wid & 3;
    const int wn   = wid >> 2;
    const int m0   = blockIdx.y * BM;
    const int n0   = blockIdx.x * BN;
    const int m0w  = wm * 32;
    const int n0w  = wn * 64;

    const float* Xb = X + (size_t)m0 * K;
    const float* Wb = W + (size_t)n0 * K;

    float D[2][8][4];
#pragma unroll
    for (int mi = 0; mi < 2; mi++)
#pragma unroll
        for (int ni = 0; ni < 8; ni++)
#pragma unroll
            for (int q = 0; q < 4; q++) D[mi][ni][q] = 0.f;

    float4 px[4], pw[4];
#pragma unroll
    for (int l = 0; l < 4; l++) {
        int idx = l * 256 + tid;
        int row = idx >> 3, col = (idx & 7) * 4;
        px[l] = *(const float4*)(Xb + (size_t)row * K + col);
        pw[l] = *(const float4*)(Wb + (size_t)row * K + col);
    }

    for (int k0 = 0; k0 < K; k0 += BK) {
#pragma unroll
        for (int l = 0; l < 4; l++) {
            int idx = l * 256 + tid;
            int row = idx >> 3, col = (idx & 7) * 4;
            Xs[row][col + 0] = f2tf32(px[l].x);
            Xs[row][col + 1] = f2tf32(px[l].y);
            Xs[row][col + 2] = f2tf32(px[l].z);
            Xs[row][col + 3] = f2tf32(px[l].w);
            Ws[row][col + 0] = f2tf32(pw[l].x);
            Ws[row][col + 1] = f2tf32(pw[l].y);
            Ws[row][col + 2] = f2tf32(pw[l].z);
            Ws[row][col + 3] = f2tf32(pw[l].w);
        }
        __syncthreads();

        if (k0 + BK < K) {
#pragma unroll
            for (int l = 0; l < 4; l++) {
                int idx = l * 256 + tid;
                int row = idx >> 3, col = (idx & 7) * 4;
                px[l] = *(const float4*)(Xb + (size_t)row * K + k0 + BK + col);
                pw[l] = *(const float4*)(Wb + (size_t)row * K + k0 + BK + col);
            }
        }

#pragma unroll
        for (int kk = 0; kk < BK; kk += 8) {
            unsigned a[2][4];
#pragma unroll
            for (int mi = 0; mi < 2; mi++) {
                a[mi][0] = Xs[m0w + mi * 16 + g][kk + tg];
                a[mi][1] = Xs[m0w + mi * 16 + 8 + g][kk + tg];
                a[mi][2] = Xs[m0w + mi * 16 + g][kk + tg + 4];
                a[mi][3] = Xs[m0w + mi * 16 + 8 + g][kk + tg + 4];
            }
#pragma unroll
            for (int ni = 0; ni < 8; ni++) {
                unsigned b0 = Ws[n0w + ni * 8 + g][kk + tg];
                unsigned b1 = Ws[n0w + ni * 8 + g][kk + tg + 4];
#pragma unroll
                for (int mi = 0; mi < 2; mi++) {
                    asm volatile(
                        "mma.sync.aligned.m16n8k8.row.col.f32.tf32.tf32.f32 "
                        "{%0,%1,%2,%3}, {%4,%5,%6,%7}, {%8,%9}, {%0,%1,%2,%3};"
                        : "+f"(D[mi][ni][0]), "+f"(D[mi][ni][1]),
                          "+f"(D[mi][ni][2]), "+f"(D[mi][ni][3])
                        : "r"(a[mi][0]), "r"(a[mi][1]), "r"(a[mi][2]), "r"(a[mi][3]),
                          "r"(b0), "r"(b1));
                }
            }
        }
        __syncthreads();
    }

#pragma unroll
    for (int ni = 0; ni < 8; ni++) {
        int n = n0 + n0w + ni * 8 + 2 * tg;
        float bvx = bias[n], bvy = bias[n + 1];
#pragma unroll
        for (int mi = 0; mi < 2; mi++) {
            int mrow = m0 + m0w + mi * 16 + g;
            float2 o0 = make_float2(D[mi][ni][0] + bvx, D[mi][ni][1] + bvy);
            float2 o1 = make_float2(D[mi][ni][2] + bvx, D[mi][ni][3] + bvy);
            *(float2*)(out + (size_t)mrow * N + n)       = o0;
            *(float2*)(out + (size_t)(mrow + 8) * N + n) = o1;
        }
    }
}

// ============================================================================
// Persistent GRU recurrence — 512 threads/CTA (16 warps/SM, 4 per SMSP).
// 128 CTAs = 32 unit-tiles x 4 batch-tiles, tile 32 batch x 16 units.
// 512 threads = 4 k-quarters x 128. Thread: 2 batch x 2 units x 3 gates
// = 12 packed f32x2 accs, 24 FMA2 per 8 LDS.128 per k4. Same smem as before.
// ============================================================================
#define RBT 32
#define RUT 16
#define HP  516
#define KS4 128
#define REC_SMEM_BYTES ((RBT * HP + 48 * HP) * 4 + 12 * 384 * 8)

__global__ __launch_bounds__(512)
void gru_rec(const float* __restrict__ xg,   // [B*T, 1536]
             const float* __restrict__ Whh,  // [1536, 512]
             const float* __restrict__ bhh,  // [1536]
             float* __restrict__ hseq,       // [B, T, 512]
             unsigned* __restrict__ ctr)
{
    extern __shared__ float sm[];
    float* h_s = sm;                                    // [RBT][HP]
    float* W_s = sm + RBT * HP;                         // [48][HP], row = g*16+u
    unsigned long long* red =
        (unsigned long long*)(sm + RBT * HP + 48 * HP); // [12][384]
    __shared__ float bh_s[48];

    const int tid = threadIdx.x;
    const int u0  = blockIdx.x * RUT;
    const int b0  = blockIdx.y * RBT;
    const unsigned nCTA = gridDim.x * gridDim.y;

    // preload W_hh rows (48 x 512) and b_hh
    for (int i = tid; i < 48 * (HID_ / 4); i += 512) {
        int rr = i >> 7;
        int c4 = i & 127;
        int g = rr >> 4, u = rr & 15;
        float4 v = *(const float4*)(Whh + (size_t)(g * HID_ + u0 + u) * HID_ + c4 * 4);
        *(float4*)&W_s[rr * HP + c4 * 4] = v;
    }
    if (tid < 48) {
        int g = tid >> 4, u = tid & 15;
        bh_s[tid] = bhh[g * HID_ + u0 + u];
    }

    const int ks  = tid >> 7;        // k-quarter 0..3
    const int r   = tid & 127;
    const int ug2 = r & 7;           // unit pair: units ug2, ug2+8
    const int bg  = r >> 3;          // 0..15 -> rows bg, bg+16
    const int kb  = ks * KS4;

    const ulonglong2* wp[2][3];
#pragma unroll
    for (int j = 0; j < 2; j++)
#pragma unroll
        for (int g = 0; g < 3; g++)
            wp[j][g] = (const ulonglong2*)(W_s + (g * 16 + ug2 + 8 * j) * HP + kb);
    const ulonglong2* hA = (const ulonglong2*)(h_s + (bg +  0) * HP + kb);
    const ulonglong2* hB = (const ulonglong2*)(h_s + (bg + 16) * HP + kb);

    for (int t = 0; t < T_; t++) {
        // ---- stage previous h tile [32 x 512] into smem ----
        if (t == 0) {
            for (int i = tid; i < RBT * (HID_ / 4); i += 512)
                *(float4*)&h_s[(i >> 7) * HP + (i & 127) * 4] =
                    make_float4(0.f, 0.f, 0.f, 0.f);
        } else {
            for (int i = tid; i < RBT * (HID_ / 4); i += 512) {
                int rr = i >> 7, c4 = i & 127;
                const float* src = hseq + ((size_t)(b0 + rr) * T_ + (t - 1)) * HID_ + c4 * 4;
                unsigned sdst = (unsigned)__cvta_generic_to_shared(&h_s[rr * HP + c4 * 4]);
                asm volatile("cp.async.cg.shared.global [%0], [%1], 16;"
                             :: "r"(sdst), "l"(src));
            }
            asm volatile("cp.async.commit_group;");
        }

        // ---- xg prefetch (ks0 only), overlapped with cp.async ----
        float xv[2][3][2];   // [unit j][gate][batch i]
        if (ks == 0) {
#pragma unroll
            for (int i = 0; i < 2; i++) {
                size_t base = ((size_t)(b0 + bg + 16 * i) * T_ + t) * NG_ + u0;
#pragma unroll
                for (int j = 0; j < 2; j++) {
                    int u = ug2 + 8 * j;
                    xv[j][0][i] = __ldg(xg + base + u);
                    xv[j][1][i] = __ldg(xg + base + 512 + u);
                    xv[j][2][i] = __ldg(xg + base + 1024 + u);
                }
            }
        }

        if (t != 0) asm volatile("cp.async.wait_group 0;");
        __syncthreads();

        unsigned long long A[2][2][3];
#pragma unroll
        for (int i = 0; i < 2; i++)
#pragma unroll
            for (int j = 0; j < 2; j++)
#pragma unroll
                for (int g = 0; g < 3; g++) A[i][j][g] = 0ull;

#pragma unroll 4
        for (int k4 = 0; k4 < KS4 / 4; k4++) {
            ulonglong2 hv0 = hA[k4];
            ulonglong2 hv1 = hB[k4];
            ulonglong2 wv[2][3];
#pragma unroll
            for (int j = 0; j < 2; j++)
#pragma unroll
                for (int g = 0; g < 3; g++) wv[j][g] = wp[j][g][k4];

#pragma unroll
            for (int j = 0; j < 2; j++)
#pragma unroll
                for (int g = 0; g < 3; g++) {
                    A[0][j][g] = fma2(hv0.x, wv[j][g].x, A[0][j][g]);
                    A[0][j][g] = fma2(hv0.y, wv[j][g].y, A[0][j][g]);
                    A[1][j][g] = fma2(hv1.x, wv[j][g].x, A[1][j][g]);
                    A[1][j][g] = fma2(hv1.y, wv[j][g].y, A[1][j][g]);
                }
        }

        // ---- cross-quarter reduction (u64, conflict-free) ----
        if (ks != 0) {
            int col = (ks - 1) * 128 + r;
#pragma unroll
            for (int i = 0; i < 2; i++)
#pragma unroll
                for (int j = 0; j < 2; j++)
#pragma unroll
                    for (int g = 0; g < 3; g++)
                        red[((i * 2 + j) * 3 + g) * 384 + col] = A[i][j][g];
        }
        __syncthreads();

        if (ks == 0) {
#pragma unroll
            for (int i = 0; i < 2; i++)
#pragma unroll
                for (int j = 0; j < 2; j++)
#pragma unroll
                    for (int g = 0; g < 3; g++) {
                        const unsigned long long* rp =
                            red + ((i * 2 + j) * 3 + g) * 384 + r;
                        A[i][j][g] = add2(A[i][j][g], rp[0]);
                        A[i][j][g] = add2(A[i][j][g], rp[128]);
                        A[i][j][g] = add2(A[i][j][g], rp[256]);
                    }

#pragma unroll
            for (int j = 0; j < 2; j++) {
                int ul = ug2 + 8 * j;
                const float br = bh_s[ul], bz = bh_s[16 + ul], bn = bh_s[32 + ul];
#pragma unroll
                for (int i = 0; i < 2; i++) {
                    float lo, hi;
                    unpack2(A[i][j][0], lo, hi); float hr = lo + hi + br;
                    unpack2(A[i][j][1], lo, hi); float hz = lo + hi + bz;
                    unpack2(A[i][j][2], lo, hi); float hn = lo + hi + bn;
                    float rr = 1.f / (1.f + __expf(-(xv[j][0][i] + hr)));
                    float zz = 1.f / (1.f + __expf(-(xv[j][1][i] + hz)));
                    float nn = tanhf(xv[j][2][i] + rr * hn);
                    float hp = h_s[(bg + 16 * i) * HP + u0 + ul];
                    int b = b0 + bg + 16 * i;
                    hseq[((size_t)b * T_ + t) * HID_ + u0 + ul] =
                        (1.f - zz) * nn + zz * hp;
                }
            }
        }
        __syncthreads();

        if (t < T_ - 1) {
            if (tid == 0) {
                __threadfence();
                atomicAdd(ctr, 1u);
                unsigned target = (unsigned)(t + 1) * nCTA;
                volatile unsigned* vc = ctr;
                while (*vc < target) { }
                __threadfence();
            }
            __syncthreads();
        }
    }
}

// ============================================================================
// Head
// ============================================================================
__global__ __launch_bounds__(64)
void out_proj(const float* __restrict__ hseq, const float* __restrict__ Wout,
              const float* __restrict__ bout, float* __restrict__ y)
{
    __shared__ float hs[HID_];
    const int b = blockIdx.x;
    const float* h = hseq + ((size_t)b * T_ + (T_ - 1)) * HID_;
    for (int i = threadIdx.x; i < HID_; i += 64) hs[i] = h[i];
    __syncthreads();

    const int o = threadIdx.x;
    float acc = bout[o];
    const float* w = Wout + (size_t)o * HID_;
#pragma unroll 4
    for (int k = 0; k < HID_; k += 4) {
        float4 wv = *(const float4*)(w + k);
        acc += hs[k] * wv.x + hs[k + 1] * wv.y + hs[k + 2] * wv.z + hs[k + 3] * wv.w;
    }
    y[b * OUT_ + o] = acc;
}

// ============================================================================
extern "C" void kernel_launch(void* const* d_in, const int* in_sizes, int n_in,
                              void* d_out, int out_size)
{
    (void)in_sizes; (void)n_in; (void)out_size;
    const float* x     = (const float*)d_in[0];
    const float* W_ih0 = (const float*)d_in[1];
    const float* W_hh0 = (const float*)d_in[2];
    const float* b_ih0 = (const float*)d_in[3];
    const float* b_hh0 = (const float*)d_in[4];
    const float* W_ih1 = (const float*)d_in[5];
    const float* W_hh1 = (const float*)d_in[6];
    const float* b_ih1 = (const float*)d_in[7];
    const float* b_hh1 = (const float*)d_in[8];
    const float* W_out = (const float*)d_in[9];
    const float* b_out = (const float*)d_in[10];
    float* y = (float*)d_out;

    float *xg, *h0, *h1;
    unsigned* ctr;
    cudaGetSymbolAddress((void**)&xg, g_xg);
    cudaGetSymbolAddress((void**)&h0, g_h0);
    cudaGetSymbolAddress((void**)&h1, g_h1);
    cudaGetSymbolAddress((void**)&ctr, g_ctr);

    cudaFuncSetAttribute(gru_rec, cudaFuncAttributeMaxDynamicSharedMemorySize,
                         REC_SMEM_BYTES);

    cudaMemsetAsync(ctr, 0, 2 * sizeof(unsigned));

    const dim3 ggrid(NG_ / BN, (B_ * T_) / BM);   // 12 x 256

    gemm_tf32<<<ggrid, 256>>>(x, W_ih0, b_ih0, xg, B_ * T_, NG_, IN_);
    gru_rec<<<dim3(HID_ / RUT, B_ / RBT), 512, REC_SMEM_BYTES>>>(xg, W_hh0, b_hh0, h0, ctr);

    gemm_tf32<<<ggrid, 256>>>(h0, W_ih1, b_ih1, xg, B_ * T_, NG_, HID_);
    gru_rec<<<dim3(HID_ / RUT, B_ / RBT), 512, REC_SMEM_BYTES>>>(xg, W_hh1, b_hh1, h1, ctr + 1);

    out_proj<<<B_, 64>>>(h1, W_out, b_out, y);
}

// round 13
// speedup vs baseline: 2.8249x; 2.8249x over previous
#include <cuda_runtime.h>
#include <cuda_bf16.h>
#include <math.h>

#define B_    128
#define T_    256
#define IN_   256
#define HID_  512
#define NG_   1536   // 3*HID
#define OUT_  64

// ---------------- scratch (static __device__, no allocation) ----------------
__device__ float    g_xg[(size_t)B_ * T_ * NG_];
__device__ float    g_h0[(size_t)B_ * T_ * HID_];
__device__ float    g_h1[(size_t)B_ * T_ * HID_];
__device__ unsigned g_hsplit[B_][HID_];          // split-bf16 h_prev (u32 = hi|lo<<16)
__device__ unsigned g_ctr[2];

// ---------------- helpers ----------------------------------------------------
__device__ __forceinline__ unsigned f2tf32(float f) {
    unsigned u;
    asm("cvt.rna.tf32.f32 %0, %1;" : "=r"(u) : "f"(f));
    return u;
}
// u32 word = (hi_bf16 low 16) | (lo_bf16 high 16); hi = truncate(x),
// lo = rn_bf16(x - hi). hi + lo reproduces x to ~2^-17 relative.
__device__ __forceinline__ unsigned splitpack(float x) {
    unsigned xb = __float_as_uint(x);
    unsigned hi = xb >> 16;
    float r = x - __uint_as_float(xb & 0xFFFF0000u);
    unsigned lo = (unsigned)__bfloat16_as_ushort(__float2bfloat16(r));
    return hi | (lo << 16);
}
__device__ __forceinline__ unsigned prmt(unsigned a, unsigned sel) {
    unsigned d;
    asm("prmt.b32 %0, %1, %2, %3;" : "=r"(d) : "r"(a), "r"(0u), "r"(sel));
    return d;
}
__device__ __forceinline__ void mma_bf16(float* d, const unsigned* a,
                                         unsigned b0, unsigned b1) {
    asm volatile(
        "mma.sync.aligned.m16n8k16.row.col.f32.bf16.bf16.f32 "
        "{%0,%1,%2,%3},{%4,%5,%6,%7},{%8,%9},{%0,%1,%2,%3};"
        : "+f"(d[0]), "+f"(d[1]), "+f"(d[2]), "+f"(d[3])
        : "r"(a[0]), "r"(a[1]), "r"(a[2]), "r"(a[3]), "r"(b0), "r"(b1));
}

// ============================================================================
// tf32 tensor-core GEMM (R6 version, proven): out = X @ W^T + bias
// 128x128x32 tile, 256 threads = 8 warps (4m x 2n), warp tile 32x64.
// ============================================================================
#define BM 128
#define BN 128
#define BK 32
#define SP 36

__global__ __launch_bounds__(256, 2)
void gemm_tf32(const float* __restrict__ X, const float* __restrict__ W,
               const float* __restrict__ bias, float* __restrict__ out,
               int M, int N, int K)
{
    __shared__ unsigned Xs[BM][SP];
    __shared__ unsigned Ws[BN][SP];

    const int tid  = threadIdx.x;
    const int lane = tid & 31;
    const int wid  = tid >> 5;
    const int g    = lane >> 2;
    const int tg   = lane & 3;
    const int wm   = wid & 3;
    const int wn   = wid >> 2;
    const int m0   = blockIdx.y * BM;
    const int n0   = blockIdx.x * BN;
    const int m0w  = wm * 32;
    const int n0w  = wn * 64;

    const float* Xb = X + (size_t)m0 * K;
    const float* Wb = W + (size_t)n0 * K;

    float D[2][8][4];
#pragma unroll
    for (int mi = 0; mi < 2; mi++)
#pragma unroll
        for (int ni = 0; ni < 8; ni++)
#pragma unroll
            for (int q = 0; q < 4; q++) D[mi][ni][q] = 0.f;

    float4 px[4], pw[4];
#pragma unroll
    for (int l = 0; l < 4; l++) {
        int idx = l * 256 + tid;
        int row = idx >> 3, col = (idx & 7) * 4;
        px[l] = *(const float4*)(Xb + (size_t)row * K + col);
        pw[l] = *(const float4*)(Wb + (size_t)row * K + col);
    }

    for (int k0 = 0; k0 < K; k0 += BK) {
#pragma unroll
        for (int l = 0; l < 4; l++) {
            int idx = l * 256 + tid;
            int row = idx >> 3, col = (idx & 7) * 4;
            Xs[row][col + 0] = f2tf32(px[l].x);
            Xs[row][col + 1] = f2tf32(px[l].y);
            Xs[row][col + 2] = f2tf32(px[l].z);
            Xs[row][col + 3] = f2tf32(px[l].w);
            Ws[row][col + 0] = f2tf32(pw[l].x);
            Ws[row][col + 1] = f2tf32(pw[l].y);
            Ws[row][col + 2] = f2tf32(pw[l].z);
            Ws[row][col + 3] = f2tf32(pw[l].w);
        }
        __syncthreads();

        if (k0 + BK < K) {
#pragma unroll
            for (int l = 0; l < 4; l++) {
                int idx = l * 256 + tid;
                int row = idx >> 3, col = (idx & 7) * 4;
                px[l] = *(const float4*)(Xb + (size_t)row * K + k0 + BK + col);
                pw[l] = *(const float4*)(Wb + (size_t)row * K + k0 + BK + col);
            }
        }

#pragma unroll
        for (int kk = 0; kk < BK; kk += 8) {
            unsigned a[2][4];
#pragma unroll
            for (int mi = 0; mi < 2; mi++) {
                a[mi][0] = Xs[m0w + mi * 16 + g][kk + tg];
                a[mi][1] = Xs[m0w + mi * 16 + 8 + g][kk + tg];
                a[mi][2] = Xs[m0w + mi * 16 + g][kk + tg + 4];
                a[mi][3] = Xs[m0w + mi * 16 + 8 + g][kk + tg + 4];
            }
#pragma unroll
            for (int ni = 0; ni < 8; ni++) {
                unsigned b0 = Ws[n0w + ni * 8 + g][kk + tg];
                unsigned b1 = Ws[n0w + ni * 8 + g][kk + tg + 4];
#pragma unroll
                for (int mi = 0; mi < 2; mi++) {
                    asm volatile(
                        "mma.sync.aligned.m16n8k8.row.col.f32.tf32.tf32.f32 "
                        "{%0,%1,%2,%3}, {%4,%5,%6,%7}, {%8,%9}, {%0,%1,%2,%3};"
                        : "+f"(D[mi][ni][0]), "+f"(D[mi][ni][1]),
                          "+f"(D[mi][ni][2]), "+f"(D[mi][ni][3])
                        : "r"(a[mi][0]), "r"(a[mi][1]), "r"(a[mi][2]), "r"(a[mi][3]),
                          "r"(b0), "r"(b1));
                }
            }
        }
        __syncthreads();
    }

#pragma unroll
    for (int ni = 0; ni < 8; ni++) {
        int n = n0 + n0w + ni * 8 + 2 * tg;
        float bvx = bias[n], bvy = bias[n + 1];
#pragma unroll
        for (int mi = 0; mi < 2; mi++) {
            int mrow = m0 + m0w + mi * 16 + g;
            float2 o0 = make_float2(D[mi][ni][0] + bvx, D[mi][ni][1] + bvy);
            float2 o1 = make_float2(D[mi][ni][2] + bvx, D[mi][ni][3] + bvy);
            *(float2*)(out + (size_t)mrow * N + n)       = o0;
            *(float2*)(out + (size_t)(mrow + 8) * N + n) = o1;
        }
    }
}

// ============================================================================
// Persistent GRU recurrence — split-bf16 tensor-core per-step GEMM (2-mma).
// 128 CTAs = 32 unit-tiles (16 units -> 48 gate cols) x 4 batch-tiles (32 rows).
// 256 threads = 8 warps: (n-half) x (k-quarter). Warp tile m32 x n24 x k'256.
// A fragments expanded hi-dup / lo-dup via PRMT so both mmas against the
// interleaved W fragment reconstruct x·w with all cross terms (~1e-5 error).
// ============================================================================
#define RBT 32
#define RUT 16
#define WP  516                       // u32 words per row (512 + 4 pad)
#define OFF_W   0                     // Wsp: 48*516 u32
#define OFF_H   (48 * WP)             // hsp: 32*516 u32
#define OFF_RED (OFF_H + 32 * WP)     // red: 4*32*50 f32
#define RED_P   50
#define REC_SMEM_BYTES ((OFF_RED + 4 * 32 * RED_P) * 4)

__global__ __launch_bounds__(256)
void gru_rec(const float* __restrict__ xg,   // [B*T, 1536]
             const float* __restrict__ Whh,  // [1536, 512]
             const float* __restrict__ bhh,  // [1536]
             float* __restrict__ hseq,       // [B, T, 512]
             unsigned* __restrict__ hsplit,  // [B_][512] split u32
             unsigned* __restrict__ ctr)
{
    extern __shared__ unsigned smu[];
    unsigned* Wsp = smu + OFF_W;     // [48][WP] split W rows (n = g*16+u)
    unsigned* hsp = smu + OFF_H;     // [32][WP] split h rows
    float*    red = (float*)(smu + OFF_RED);   // [4][32][RED_P]
    __shared__ float bh_s[48];

    const int tid = threadIdx.x;
    const int u0  = blockIdx.x * RUT;
    const int b0  = blockIdx.y * RBT;
    const unsigned nCTA = gridDim.x * gridDim.y;

    // ---- preamble: split-convert W_hh rows into smem (once) ----
    for (int i = tid; i < 48 * (HID_ / 4); i += 256) {
        int row = i >> 7;            // 0..47 = g*16+u
        int c4  = i & 127;
        int g = row >> 4, u = row & 15;
        float4 v = *(const float4*)(Whh + (size_t)(g * HID_ + u0 + u) * HID_ + c4 * 4);
        unsigned* dst = Wsp + row * WP + c4 * 4;
        dst[0] = splitpack(v.x); dst[1] = splitpack(v.y);
        dst[2] = splitpack(v.z); dst[3] = splitpack(v.w);
    }
    if (tid < 48) {
        int g = tid >> 4, u = tid & 15;
        bh_s[tid] = bhh[g * HID_ + u0 + u];
    }

    const int lane = tid & 31;
    const int wid  = tid >> 5;
    const int g    = lane >> 2;      // 0..7
    const int c    = lane & 3;       // 0..3
    const int kq   = wid >> 1;       // k-quarter 0..3
    const int nh   = wid & 1;        // n-half 0/1
    const int wb0  = kq * 128;       // word base of this quarter

    // outputs owned by this thread (epilogue): o = tid, tid+256
    const int ob[2] = { tid >> 4, (tid + 256) >> 4 };        // batch row 0..31
    const int ou[2] = { tid & 15, (tid + 256) & 15 };        // unit 0..15

    for (int t = 0; t < T_; t++) {
        // ---- stage h_prev split tile [32][512] u32 into smem ----
        if (t == 0) {
            for (int i = tid; i < 32 * 128; i += 256) {
                unsigned* dst = hsp + (i >> 7) * WP + (i & 127) * 4;
                dst[0] = 0u; dst[1] = 0u; dst[2] = 0u; dst[3] = 0u;
            }
        } else {
            for (int i = tid; i < 32 * 128; i += 256) {
                int row = i >> 7, c4 = i & 127;
                const unsigned* src = &hsplit[(size_t)(b0 + row) * HID_ + c4 * 4];
                unsigned sdst = (unsigned)__cvta_generic_to_shared(hsp + row * WP + c4 * 4);
                asm volatile("cp.async.cg.shared.global [%0], [%1], 16;"
                             :: "r"(sdst), "l"(src));
            }
            asm volatile("cp.async.commit_group;");
        }

        // ---- prefetch xg[t] and exact h_prev for owned outputs ----
        float xr[2], xz[2], xn[2], hp[2];
#pragma unroll
        for (int e = 0; e < 2; e++) {
            size_t xb = ((size_t)(b0 + ob[e]) * T_ + t) * NG_ + u0 + ou[e];
            xr[e] = __ldg(xg + xb);
            xz[e] = __ldg(xg + xb + 512);
            xn[e] = __ldg(xg + xb + 1024);
            hp[e] = (t == 0) ? 0.f
                  : __ldg(hseq + ((size_t)(b0 + ob[e]) * T_ + (t - 1)) * HID_ + u0 + ou[e]);
        }

        if (t != 0) asm volatile("cp.async.wait_group 0;");
        __syncthreads();

        // ---- mma phase: warp = (nh, kq); m32 x n24 x k'256, 2-mma split ----
        float D[2][3][4];
#pragma unroll
        for (int mi = 0; mi < 2; mi++)
#pragma unroll
            for (int nt = 0; nt < 3; nt++)
#pragma unroll
                for (int q = 0; q < 4; q++) D[mi][nt][q] = 0.f;

#pragma unroll 2
        for (int ki = 0; ki < 16; ki++) {
            int wb = wb0 + ki * 8;
            unsigned a[2][4], ahi[2][4], alo[2][4];
#pragma unroll
            for (int mi = 0; mi < 2; mi++) {
                a[mi][0] = hsp[(mi * 16 + g) * WP + wb + c];
                a[mi][1] = hsp[(mi * 16 + 8 + g) * WP + wb + c];
                a[mi][2] = hsp[(mi * 16 + g) * WP + wb + c + 4];
                a[mi][3] = hsp[(mi * 16 + 8 + g) * WP + wb + c + 4];
#pragma unroll
                for (int q = 0; q < 4; q++) {
                    ahi[mi][q] = prmt(a[mi][q], 0x1010u);   // (hi,hi)
                    alo[mi][q] = prmt(a[mi][q], 0x3232u);   // (lo,lo)
                }
            }
#pragma unroll
            for (int nt = 0; nt < 3; nt++) {
                int rowN = nh * 24 + nt * 8 + g;
                unsigned b0w = Wsp[rowN * WP + wb + c];
                unsigned b1w = Wsp[rowN * WP + wb + c + 4];
#pragma unroll
                for (int mi = 0; mi < 2; mi++) {
                    mma_bf16(D[mi][nt], ahi[mi], b0w, b1w);  // hi_x * w
                    mma_bf16(D[mi][nt], alo[mi], b0w, b1w);  // lo_x * w
                }
            }
        }

        // ---- store per-quarter partials ----
#pragma unroll
        for (int mi = 0; mi < 2; mi++)
#pragma unroll
            for (int nt = 0; nt < 3; nt++) {
                int col = nh * 24 + nt * 8 + 2 * c;
                int r0 = mi * 16 + g;
                *(float2*)&red[(kq * 32 + r0) * RED_P + col] =
                    make_float2(D[mi][nt][0], D[mi][nt][1]);
                *(float2*)&red[(kq * 32 + r0 + 8) * RED_P + col] =
                    make_float2(D[mi][nt][2], D[mi][nt][3]);
            }
        __syncthreads();

        // ---- epilogue: 2 outputs per thread ----
#pragma unroll
        for (int e = 0; e < 2; e++) {
            int b = ob[e], u = ou[e];
            float hr = bh_s[u], hz = bh_s[16 + u], hn = bh_s[32 + u];
#pragma unroll
            for (int q = 0; q < 4; q++) {
                const float* rp = red + (q * 32 + b) * RED_P;
                hr += rp[u];
                hz += rp[16 + u];
                hn += rp[32 + u];
            }
            float rr = 1.f / (1.f + __expf(-(xr[e] + hr)));
            float zz = 1.f / (1.f + __expf(-(xz[e] + hz)));
            float nn = tanhf(xn[e] + rr * hn);
            float hv = (1.f - zz) * nn + zz * hp[e];
            hseq[((size_t)(b0 + b) * T_ + t) * HID_ + u0 + u] = hv;
            hsplit[(size_t)(b0 + b) * HID_ + u0 + u] = splitpack(hv);
        }
        __syncthreads();   // red/hsp reads complete before next step overwrites

        if (t < T_ - 1) {
            if (tid == 0) {
                __threadfence();
                atomicAdd(ctr, 1u);
                unsigned target = (unsigned)(t + 1) * nCTA;
                volatile unsigned* vc = ctr;
                while (*vc < target) { }
                __threadfence();
            }
            __syncthreads();
        }
    }
}

// ============================================================================
// Head
// ============================================================================
__global__ __launch_bounds__(64)
void out_proj(const float* __restrict__ hseq, const float* __restrict__ Wout,
              const float* __restrict__ bout, float* __restrict__ y)
{
    __shared__ float hs[HID_];
    const int b = blockIdx.x;
    const float* h = hseq + ((size_t)b * T_ + (T_ - 1)) * HID_;
    for (int i = threadIdx.x; i < HID_; i += 64) hs[i] = h[i];
    __syncthreads();

    const int o = threadIdx.x;
    float acc = bout[o];
    const float* w = Wout + (size_t)o * HID_;
#pragma unroll 4
    for (int k = 0; k < HID_; k += 4) {
        float4 wv = *(const float4*)(w + k);
        acc += hs[k] * wv.x + hs[k + 1] * wv.y + hs[k + 2] * wv.z + hs[k + 3] * wv.w;
    }
    y[b * OUT_ + o] = acc;
}

// ============================================================================
extern "C" void kernel_launch(void* const* d_in, const int* in_sizes, int n_in,
                              void* d_out, int out_size)
{
    (void)in_sizes; (void)n_in; (void)out_size;
    const float* x     = (const float*)d_in[0];
    const float* W_ih0 = (const float*)d_in[1];
    const float* W_hh0 = (const float*)d_in[2];
    const float* b_ih0 = (const float*)d_in[3];
    const float* b_hh0 = (const float*)d_in[4];
    const float* W_ih1 = (const float*)d_in[5];
    const float* W_hh1 = (const float*)d_in[6];
    const float* b_ih1 = (const float*)d_in[7];
    const float* b_hh1 = (const float*)d_in[8];
    const float* W_out = (const float*)d_in[9];
    const float* b_out = (const float*)d_in[10];
    float* y = (float*)d_out;

    float *xg, *h0, *h1;
    unsigned *ctr, *hsp;
    cudaGetSymbolAddress((void**)&xg, g_xg);
    cudaGetSymbolAddress((void**)&h0, g_h0);
    cudaGetSymbolAddress((void**)&h1, g_h1);
    cudaGetSymbolAddress((void**)&ctr, g_ctr);
    cudaGetSymbolAddress((void**)&hsp, g_hsplit);

    cudaFuncSetAttribute(gru_rec, cudaFuncAttributeMaxDynamicSharedMemorySize,
                         REC_SMEM_BYTES);

    cudaMemsetAsync(ctr, 0, 2 * sizeof(unsigned));

    const dim3 ggrid(NG_ / BN, (B_ * T_) / BM);   // 12 x 256

    gemm_tf32<<<ggrid, 256>>>(x, W_ih0, b_ih0, xg, B_ * T_, NG_, IN_);
    gru_rec<<<dim3(HID_ / RUT, B_ / RBT), 256, REC_SMEM_BYTES>>>(
        xg, W_hh0, b_hh0, h0, hsp, ctr);

    gemm_tf32<<<ggrid, 256>>>(h0, W_ih1, b_ih1, xg, B_ * T_, NG_, HID_);
    gru_rec<<<dim3(HID_ / RUT, B_ / RBT), 256, REC_SMEM_BYTES>>>(
        xg, W_hh1, b_hh1, h1, hsp, ctr + 1);

    out_proj<<<B_, 64>>>(h1, W_out, b_out, y);
}

// round 15
// speedup vs baseline: 2.8309x; 1.0021x over previous
#include <cuda_runtime.h>
#include <cuda_bf16.h>
#include <math.h>

#define B_    128
#define T_    256
#define IN_   256
#define HID_  512
#define NG_   1536   // 3*HID
#define OUT_  64

// ---------------- scratch (static __device__, no allocation) ----------------
__device__ float    g_xg[(size_t)B_ * T_ * NG_];
__device__ float    g_h0[(size_t)B_ * T_ * HID_];
__device__ float    g_h1[(size_t)B_ * T_ * HID_];
__device__ unsigned g_hsplit[B_][HID_];          // split-bf16 h_prev (u32 = hi|lo<<16)
__device__ unsigned g_ctr[2];

// ---------------- helpers ----------------------------------------------------
__device__ __forceinline__ unsigned f2tf32(float f) {
    unsigned u;
    asm("cvt.rna.tf32.f32 %0, %1;" : "=r"(u) : "f"(f));
    return u;
}
// u32 word = (hi_bf16 low 16) | (lo_bf16 high 16); hi = truncate(x),
// lo = rn_bf16(x - hi). hi + lo reproduces x to ~2^-17 relative.
__device__ __forceinline__ unsigned splitpack(float x) {
    unsigned xb = __float_as_uint(x);
    unsigned hi = xb >> 16;
    float r = x - __uint_as_float(xb & 0xFFFF0000u);
    unsigned lo = (unsigned)__bfloat16_as_ushort(__float2bfloat16(r));
    return hi | (lo << 16);
}
__device__ __forceinline__ unsigned prmt(unsigned a, unsigned sel) {
    unsigned d;
    asm("prmt.b32 %0, %1, %2, %3;" : "=r"(d) : "r"(a), "r"(0u), "r"(sel));
    return d;
}
__device__ __forceinline__ void mma_bf16(float* d, const unsigned* a,
                                         unsigned b0, unsigned b1) {
    asm volatile(
        "mma.sync.aligned.m16n8k16.row.col.f32.bf16.bf16.f32 "
        "{%0,%1,%2,%3},{%4,%5,%6,%7},{%8,%9},{%0,%1,%2,%3};"
        : "+f"(d[0]), "+f"(d[1]), "+f"(d[2]), "+f"(d[3])
        : "r"(a[0]), "r"(a[1]), "r"(a[2]), "r"(a[3]), "r"(b0), "r"(b1));
}
__device__ __forceinline__ void ldmatrix_x4(unsigned& r0, unsigned& r1,
                                            unsigned& r2, unsigned& r3,
                                            unsigned addr) {
    asm volatile("ldmatrix.sync.aligned.m8n8.x4.shared.b16 {%0,%1,%2,%3}, [%4];"
                 : "=r"(r0), "=r"(r1), "=r"(r2), "=r"(r3) : "r"(addr));
}
__device__ __forceinline__ void ldmatrix_x2(unsigned& r0, unsigned& r1,
                                            unsigned addr) {
    asm volatile("ldmatrix.sync.aligned.m8n8.x2.shared.b16 {%0,%1}, [%2];"
                 : "=r"(r0), "=r"(r1) : "r"(addr));
}

// ============================================================================
// tf32 tensor-core GEMM (proven): out = X @ W^T + bias
// 128x128x32 tile, 256 threads = 8 warps (4m x 2n), warp tile 32x64.
// ============================================================================
#define BM 128
#define BN 128
#define BK 32
#define SP 36

__global__ __launch_bounds__(256, 2)
void gemm_tf32(const float* __restrict__ X, const float* __restrict__ W,
               const float* __restrict__ bias, float* __restrict__ out,
               int M, int N, int K)
{
    __shared__ unsigned Xs[BM][SP];
    __shared__ unsigned Ws[BN][SP];

    const int tid  = threadIdx.x;
    const int lane = tid & 31;
    const int wid  = tid >> 5;
    const int g    = lane >> 2;
    const int tg   = lane & 3;
    const int wm   = wid & 3;
    const int wn   = wid >> 2;
    const int m0   = blockIdx.y * BM;
    const int n0   = blockIdx.x * BN;
    const int m0w  = wm * 32;
    const int n0w  = wn * 64;

    const float* Xb = X + (size_t)m0 * K;
    const float* Wb = W + (size_t)n0 * K;

    float D[2][8][4];
#pragma unroll
    for (int mi = 0; mi < 2; mi++)
#pragma unroll
        for (int ni = 0; ni < 8; ni++)
#pragma unroll
            for (int q = 0; q < 4; q++) D[mi][ni][q] = 0.f;

    float4 px[4], pw[4];
#pragma unroll
    for (int l = 0; l < 4; l++) {
        int idx = l * 256 + tid;
        int row = idx >> 3, col = (idx & 7) * 4;
        px[l] = *(const float4*)(Xb + (size_t)row * K + col);
        pw[l] = *(const float4*)(Wb + (size_t)row * K + col);
    }

    for (int k0 = 0; k0 < K; k0 += BK) {
#pragma unroll
        for (int l = 0; l < 4; l++) {
            int idx = l * 256 + tid;
            int row = idx >> 3, col = (idx & 7) * 4;
            Xs[row][col + 0] = f2tf32(px[l].x);
            Xs[row][col + 1] = f2tf32(px[l].y);
            Xs[row][col + 2] = f2tf32(px[l].z);
            Xs[row][col + 3] = f2tf32(px[l].w);
            Ws[row][col + 0] = f2tf32(pw[l].x);
            Ws[row][col + 1] = f2tf32(pw[l].y);
            Ws[row][col + 2] = f2tf32(pw[l].z);
            Ws[row][col + 3] = f2tf32(pw[l].w);
        }
        __syncthreads();

        if (k0 + BK < K) {
#pragma unroll
            for (int l = 0; l < 4; l++) {
                int idx = l * 256 + tid;
                int row = idx >> 3, col = (idx & 7) * 4;
                px[l] = *(const float4*)(Xb + (size_t)row * K + k0 + BK + col);
                pw[l] = *(const float4*)(Wb + (size_t)row * K + k0 + BK + col);
            }
        }

#pragma unroll
        for (int kk = 0; kk < BK; kk += 8) {
            unsigned a[2][4];
#pragma unroll
            for (int mi = 0; mi < 2; mi++) {
                a[mi][0] = Xs[m0w + mi * 16 + g][kk + tg];
                a[mi][1] = Xs[m0w + mi * 16 + 8 + g][kk + tg];
                a[mi][2] = Xs[m0w + mi * 16 + g][kk + tg + 4];
                a[mi][3] = Xs[m0w + mi * 16 + 8 + g][kk + tg + 4];
            }
#pragma unroll
            for (int ni = 0; ni < 8; ni++) {
                unsigned b0 = Ws[n0w + ni * 8 + g][kk + tg];
                unsigned b1 = Ws[n0w + ni * 8 + g][kk + tg + 4];
#pragma unroll
                for (int mi = 0; mi < 2; mi++) {
                    asm volatile(
                        "mma.sync.aligned.m16n8k8.row.col.f32.tf32.tf32.f32 "
                        "{%0,%1,%2,%3}, {%4,%5,%6,%7}, {%8,%9}, {%0,%1,%2,%3};"
                        : "+f"(D[mi][ni][0]), "+f"(D[mi][ni][1]),
                          "+f"(D[mi][ni][2]), "+f"(D[mi][ni][3])
                        : "r"(a[mi][0]), "r"(a[mi][1]), "r"(a[mi][2]), "r"(a[mi][3]),
                          "r"(b0), "r"(b1));
                }
            }
        }
        __syncthreads();
    }

#pragma unroll
    for (int ni = 0; ni < 8; ni++) {
        int n = n0 + n0w + ni * 8 + 2 * tg;
        float bvx = bias[n], bvy = bias[n + 1];
#pragma unroll
        for (int mi = 0; mi < 2; mi++) {
            int mrow = m0 + m0w + mi * 16 + g;
            float2 o0 = make_float2(D[mi][ni][0] + bvx, D[mi][ni][1] + bvy);
            float2 o1 = make_float2(D[mi][ni][2] + bvx, D[mi][ni][3] + bvy);
            *(float2*)(out + (size_t)mrow * N + n)       = o0;
            *(float2*)(out + (size_t)(mrow + 8) * N + n) = o1;
        }
    }
}

// ============================================================================
// Persistent GRU recurrence — split-bf16 tensor-core per-step GEMM (2-mma),
// ldmatrix fragments, register-carried h_prev, pre-barrier xg prefetch.
// 128 CTAs = 32 unit-tiles (16 units -> 48 gate cols) x 4 batch-tiles (32 rows).
// 256 threads = 8 warps: (n-half) x (k-quarter). Warp tile m32 x n24 x k'256.
// ============================================================================
#define RBT 32
#define RUT 16
#define WP  516                       // u32 words per row (512 + 4 pad)
#define OFF_W   0                     // Wsp: 48*516 u32
#define OFF_H   (48 * WP)             // hsp: 32*516 u32
#define OFF_RED (OFF_H + 32 * WP)     // red: 4*32*50 f32
#define RED_P   50
#define REC_SMEM_BYTES ((OFF_RED + 4 * 32 * RED_P) * 4)

__global__ __launch_bounds__(256)
void gru_rec(const float* __restrict__ xg,   // [B*T, 1536]
             const float* __restrict__ Whh,  // [1536, 512]
             const float* __restrict__ bhh,  // [1536]
             float* __restrict__ hseq,       // [B, T, 512]
             unsigned* __restrict__ hsplit,  // [B_][512] split u32
             unsigned* __restrict__ ctr)
{
    extern __shared__ unsigned smu[];
    unsigned* Wsp = smu + OFF_W;     // [48][WP] split W rows (n = g*16+u)
    unsigned* hsp = smu + OFF_H;     // [32][WP] split h rows
    float*    red = (float*)(smu + OFF_RED);   // [4][32][RED_P]
    __shared__ float bh_s[48];

    const int tid = threadIdx.x;
    const int u0  = blockIdx.x * RUT;
    const int b0  = blockIdx.y * RBT;
    const unsigned nCTA = gridDim.x * gridDim.y;

    // ---- preamble: split-convert W_hh rows into smem (once) ----
    for (int i = tid; i < 48 * (HID_ / 4); i += 256) {
        int row = i >> 7;            // 0..47 = g*16+u
        int c4  = i & 127;
        int g = row >> 4, u = row & 15;
        float4 v = *(const float4*)(Whh + (size_t)(g * HID_ + u0 + u) * HID_ + c4 * 4);
        unsigned* dst = Wsp + row * WP + c4 * 4;
        dst[0] = splitpack(v.x); dst[1] = splitpack(v.y);
        dst[2] = splitpack(v.z); dst[3] = splitpack(v.w);
    }
    if (tid < 48) {
        int g = tid >> 4, u = tid & 15;
        bh_s[tid] = bhh[g * HID_ + u0 + u];
    }

    const int lane = tid & 31;
    const int wid  = tid >> 5;
    const int g    = lane >> 2;      // 0..7
    const int c    = lane & 3;       // 0..3
    const int kq   = wid >> 1;       // k-quarter 0..3
    const int nh   = wid & 1;        // n-half 0/1
    const int wb0  = kq * 128;       // word base of this quarter

    // ldmatrix per-thread base addresses (shared space, bytes)
    const int r8  = lane & 7;
    const int sel = lane >> 3;       // 0..3
    unsigned hsp_sh = (unsigned)__cvta_generic_to_shared(hsp);
    unsigned wsp_sh = (unsigned)__cvta_generic_to_shared(Wsp);
    unsigned aBase[2];
#pragma unroll
    for (int mi = 0; mi < 2; mi++)
        aBase[mi] = hsp_sh +
            (((mi * 16 + (sel & 1) * 8 + r8) * WP + (sel >> 1) * 4) << 2);
    unsigned wBase[3];
#pragma unroll
    for (int nt = 0; nt < 3; nt++)
        wBase[nt] = wsp_sh +
            (((nh * 24 + nt * 8 + r8) * WP + (sel & 1) * 4) << 2);

    // outputs owned by this thread (epilogue): o = tid, tid+256
    const int ob[2] = { tid >> 4, (tid + 256) >> 4 };        // batch row 0..31
    const int ou[2] = { tid & 15, (tid + 256) & 15 };        // unit 0..15

    // register-carried state
    float hp[2] = {0.f, 0.f};        // exact h_prev for owned outputs
    float xr[2], xz[2], xn[2];       // current-step xg
#pragma unroll
    for (int e = 0; e < 2; e++) {
        size_t xb = ((size_t)(b0 + ob[e]) * T_) * NG_ + u0 + ou[e];
        xr[e] = __ldg(xg + xb);
        xz[e] = __ldg(xg + xb + 512);
        xn[e] = __ldg(xg + xb + 1024);
    }

    for (int t = 0; t < T_; t++) {
        // ---- stage h_prev split tile [32][512] u32 into smem ----
        if (t == 0) {
            for (int i = tid; i < 32 * 128; i += 256) {
                unsigned* dst = hsp + (i >> 7) * WP + (i & 127) * 4;
                dst[0] = 0u; dst[1] = 0u; dst[2] = 0u; dst[3] = 0u;
            }
        } else {
            for (int i = tid; i < 32 * 128; i += 256) {
                int row = i >> 7, c4 = i & 127;
                const unsigned* src = &hsplit[(size_t)(b0 + row) * HID_ + c4 * 4];
                unsigned sdst = (unsigned)__cvta_generic_to_shared(hsp + row * WP + c4 * 4);
                asm volatile("cp.async.cg.shared.global [%0], [%1], 16;"
                             :: "r"(sdst), "l"(src));
            }
            asm volatile("cp.async.commit_group;");
            asm volatile("cp.async.wait_group 0;");
        }
        __syncthreads();

        // ---- mma phase: warp = (nh, kq); m32 x n24 x k'256, 2-mma split ----
        float D[2][3][4];
#pragma unroll
        for (int mi = 0; mi < 2; mi++)
#pragma unroll
            for (int nt = 0; nt < 3; nt++)
#pragma unroll
                for (int q = 0; q < 4; q++) D[mi][nt][q] = 0.f;

#pragma unroll 2
        for (int ki = 0; ki < 16; ki++) {
            unsigned koff = (unsigned)((wb0 + ki * 8) << 2);
            unsigned a[2][4], ahi[2][4], alo[2][4];
#pragma unroll
            for (int mi = 0; mi < 2; mi++) {
                ldmatrix_x4(a[mi][0], a[mi][1], a[mi][2], a[mi][3],
                            aBase[mi] + koff);
#pragma unroll
                for (int q = 0; q < 4; q++) {
                    ahi[mi][q] = prmt(a[mi][q], 0x1010u);   // (hi,hi)
                    alo[mi][q] = prmt(a[mi][q], 0x3232u);   // (lo,lo)
                }
            }
            unsigned bw[3][2];
#pragma unroll
            for (int nt = 0; nt < 3; nt++)
                ldmatrix_x2(bw[nt][0], bw[nt][1], wBase[nt] + koff);
#pragma unroll
            for (int nt = 0; nt < 3; nt++)
#pragma unroll
                for (int mi = 0; mi < 2; mi++) {
                    mma_bf16(D[mi][nt], ahi[mi], bw[nt][0], bw[nt][1]);
                    mma_bf16(D[mi][nt], alo[mi], bw[nt][0], bw[nt][1]);
                }
        }

        // ---- store per-quarter partials ----
#pragma unroll
        for (int mi = 0; mi < 2; mi++)
#pragma unroll
            for (int nt = 0; nt < 3; nt++) {
                int col = nh * 24 + nt * 8 + 2 * c;
                int r0 = mi * 16 + g;
                *(float2*)&red[(kq * 32 + r0) * RED_P + col] =
                    make_float2(D[mi][nt][0], D[mi][nt][1]);
                *(float2*)&red[(kq * 32 + r0 + 8) * RED_P + col] =
                    make_float2(D[mi][nt][2], D[mi][nt][3]);
            }
        __syncthreads();

        // ---- prefetch next-step xg (overlaps epilogue + barrier + staging) ----
        float nxr[2], nxz[2], nxn[2];
        if (t < T_ - 1) {
#pragma unroll
            for (int e = 0; e < 2; e++) {
                size_t xb = ((size_t)(b0 + ob[e]) * T_ + (t + 1)) * NG_ + u0 + ou[e];
                nxr[e] = __ldg(xg + xb);
                nxz[e] = __ldg(xg + xb + 512);
                nxn[e] = __ldg(xg + xb + 1024);
            }
        }

        // ---- epilogue: 2 outputs per thread ----
#pragma unroll
        for (int e = 0; e < 2; e++) {
            int b = ob[e], u = ou[e];
            float hr = bh_s[u], hz = bh_s[16 + u], hn = bh_s[32 + u];
#pragma unroll
            for (int q = 0; q < 4; q++) {
                const float* rp = red + (q * 32 + b) * RED_P;
                hr += rp[u];
                hz += rp[16 + u];
                hn += rp[32 + u];
            }
            float rr = 1.f / (1.f + __expf(-(xr[e] + hr)));
            float zz = 1.f / (1.f + __expf(-(xz[e] + hz)));
            float nn = tanhf(xn[e] + rr * hn);
            float hv = (1.f - zz) * nn + zz * hp[e];
            hseq[((size_t)(b0 + b) * T_ + t) * HID_ + u0 + u] = hv;
            hsplit[(size_t)(b0 + b) * HID_ + u0 + u] = splitpack(hv);
            hp[e] = hv;
        }
#pragma unroll
        for (int e = 0; e < 2; e++) { xr[e] = nxr[e]; xz[e] = nxz[e]; xn[e] = nxn[e]; }
        __syncthreads();   // red/hsp reads complete before next step overwrites

        if (t < T_ - 1) {
            if (tid == 0) {
                __threadfence();
                atomicAdd(ctr, 1u);
                unsigned target = (unsigned)(t + 1) * nCTA;
                volatile unsigned* vc = ctr;
                while (*vc < target) { }
                __threadfence();
            }
            __syncthreads();
        }
    }
}

// ============================================================================
// Head
// ============================================================================
__global__ __launch_bounds__(64)
void out_proj(const float* __restrict__ hseq, const float* __restrict__ Wout,
              const float* __restrict__ bout, float* __restrict__ y)
{
    __shared__ float hs[HID_];
    const int b = blockIdx.x;
    const float* h = hseq + ((size_t)b * T_ + (T_ - 1)) * HID_;
    for (int i = threadIdx.x; i < HID_; i += 64) hs[i] = h[i];
    __syncthreads();

    const int o = threadIdx.x;
    float acc = bout[o];
    const float* w = Wout + (size_t)o * HID_;
#pragma unroll 4
    for (int k = 0; k < HID_; k += 4) {
        float4 wv = *(const float4*)(w + k);
        acc += hs[k] * wv.x + hs[k + 1] * wv.y + hs[k + 2] * wv.z + hs[k + 3] * wv.w;
    }
    y[b * OUT_ + o] = acc;
}

// ============================================================================
extern "C" void kernel_launch(void* const* d_in, const int* in_sizes, int n_in,
                              void* d_out, int out_size)
{
    (void)in_sizes; (void)n_in; (void)out_size;
    const float* x     = (const float*)d_in[0];
    const float* W_ih0 = (const float*)d_in[1];
    const float* W_hh0 = (const float*)d_in[2];
    const float* b_ih0 = (const float*)d_in[3];
    const float* b_hh0 = (const float*)d_in[4];
    const float* W_ih1 = (const float*)d_in[5];
    const float* W_hh1 = (const float*)d_in[6];
    const float* b_ih1 = (const float*)d_in[7];
    const float* b_hh1 = (const float*)d_in[8];
    const float* W_out = (const float*)d_in[9];
    const float* b_out = (const float*)d_in[10];
    float* y = (float*)d_out;

    float *xg, *h0, *h1;
    unsigned *ctr, *hsp;
    cudaGetSymbolAddress((void**)&xg, g_xg);
    cudaGetSymbolAddress((void**)&h0, g_h0);
    cudaGetSymbolAddress((void**)&h1, g_h1);
    cudaGetSymbolAddress((void**)&ctr, g_ctr);
    cudaGetSymbolAddress((void**)&hsp, g_hsplit);

    cudaFuncSetAttribute(gru_rec, cudaFuncAttributeMaxDynamicSharedMemorySize,
                         REC_SMEM_BYTES);

    cudaMemsetAsync(ctr, 0, 2 * sizeof(unsigned));

    const dim3 ggrid(NG_ / BN, (B_ * T_) / BM);   // 12 x 256

    gemm_tf32<<<ggrid, 256>>>(x, W_ih0, b_ih0, xg, B_ * T_, NG_, IN_);
    gru_rec<<<dim3(HID_ / RUT, B_ / RBT), 256, REC_SMEM_BYTES>>>(
        xg, W_hh0, b_hh0, h0, hsp, ctr);

    gemm_tf32<<<ggrid, 256>>>(h0, W_ih1, b_ih1, xg, B_ * T_, NG_, HID_);
    gru_rec<<<dim3(HID_ / RUT, B_ / RBT), 256, REC_SMEM_BYTES>>>(
        xg, W_hh1, b_hh1, h1, hsp, ctr + 1);

    out_proj<<<B_, 64>>>(h1, W_out, b_out, y);
}

// round 16
// speedup vs baseline: 2.9857x; 1.0547x over previous
#include <cuda_runtime.h>
#include <cuda_bf16.h>
#include <math.h>

#define B_    128
#define T_    256
#define IN_   256
#define HID_  512
#define NG_   1536   // 3*HID
#define OUT_  64

// ---------------- scratch (static __device__, no allocation) ----------------
__device__ float    g_xg[(size_t)B_ * T_ * NG_];
__device__ float    g_h0[(size_t)B_ * T_ * HID_];
__device__ float    g_h1[(size_t)B_ * T_ * HID_];
__device__ unsigned g_hhi[B_][HID_ / 2];         // pair-packed hi bf16 of h_prev
__device__ unsigned g_hlo[B_][HID_ / 2];         // pair-packed lo bf16 of h_prev
__device__ unsigned g_ctr[2];

// ---------------- helpers ----------------------------------------------------
__device__ __forceinline__ unsigned f2tf32(float f) {
    unsigned u;
    asm("cvt.rna.tf32.f32 %0, %1;" : "=r"(u) : "f"(f));
    return u;
}
// hi = truncate-to-bf16(x) (top 16 bits); lo = rn_bf16(x - hi)
__device__ __forceinline__ void split2(float x, unsigned& hi, unsigned& lo) {
    unsigned xb = __float_as_uint(x);
    hi = xb >> 16;
    float r = x - __uint_as_float(xb & 0xFFFF0000u);
    lo = (unsigned)__bfloat16_as_ushort(__float2bfloat16(r));
}
__device__ __forceinline__ void mma_bf16(float* d, const unsigned* a,
                                         unsigned b0, unsigned b1) {
    asm volatile(
        "mma.sync.aligned.m16n8k16.row.col.f32.bf16.bf16.f32 "
        "{%0,%1,%2,%3},{%4,%5,%6,%7},{%8,%9},{%0,%1,%2,%3};"
        : "+f"(d[0]), "+f"(d[1]), "+f"(d[2]), "+f"(d[3])
        : "r"(a[0]), "r"(a[1]), "r"(a[2]), "r"(a[3]), "r"(b0), "r"(b1));
}
__device__ __forceinline__ void ldmatrix_x4(unsigned* r, unsigned addr) {
    asm volatile("ldmatrix.sync.aligned.m8n8.x4.shared.b16 {%0,%1,%2,%3}, [%4];"
                 : "=r"(r[0]), "=r"(r[1]), "=r"(r[2]), "=r"(r[3]) : "r"(addr));
}
__device__ __forceinline__ void ldmatrix_x2(unsigned& r0, unsigned& r1,
                                            unsigned addr) {
    asm volatile("ldmatrix.sync.aligned.m8n8.x2.shared.b16 {%0,%1}, [%2];"
                 : "=r"(r0), "=r"(r1) : "r"(addr));
}

// ============================================================================
// tf32 tensor-core GEMM (proven): out = X @ W^T + bias
// 128x128x32 tile, 256 threads = 8 warps (4m x 2n), warp tile 32x64.
// ============================================================================
#define BM 128
#define BN 128
#define BK 32
#define SP 36

__global__ __launch_bounds__(256, 2)
void gemm_tf32(const float* __restrict__ X, const float* __restrict__ W,
               const float* __restrict__ bias, float* __restrict__ out,
               int M, int N, int K)
{
    __shared__ unsigned Xs[BM][SP];
    __shared__ unsigned Ws[BN][SP];

    const int tid  = threadIdx.x;
    const int lane = tid & 31;
    const int wid  = tid >> 5;
    const int g    = lane >> 2;
    const int tg   = lane & 3;
    const int wm   = wid & 3;
    const int wn   = wid >> 2;
    const int m0   = blockIdx.y * BM;
    const int n0   = blockIdx.x * BN;
    const int m0w  = wm * 32;
    const int n0w  = wn * 64;

    const float* Xb = X + (size_t)m0 * K;
    const float* Wb = W + (size_t)n0 * K;

    float D[2][8][4];
#pragma unroll
    for (int mi = 0; mi < 2; mi++)
#pragma unroll
        for (int ni = 0; ni < 8; ni++)
#pragma unroll
            for (int q = 0; q < 4; q++) D[mi][ni][q] = 0.f;

    float4 px[4], pw[4];
#pragma unroll
    for (int l = 0; l < 4; l++) {
        int idx = l * 256 + tid;
        int row = idx >> 3, col = (idx & 7) * 4;
        px[l] = *(const float4*)(Xb + (size_t)row * K + col);
        pw[l] = *(const float4*)(Wb + (size_t)row * K + col);
    }

    for (int k0 = 0; k0 < K; k0 += BK) {
#pragma unroll
        for (int l = 0; l < 4; l++) {
            int idx = l * 256 + tid;
            int row = idx >> 3, col = (idx & 7) * 4;
            Xs[row][col + 0] = f2tf32(px[l].x);
            Xs[row][col + 1] = f2tf32(px[l].y);
            Xs[row][col + 2] = f2tf32(px[l].z);
            Xs[row][col + 3] = f2tf32(px[l].w);
            Ws[row][col + 0] = f2tf32(pw[l].x);
            Ws[row][col + 1] = f2tf32(pw[l].y);
            Ws[row][col + 2] = f2tf32(pw[l].z);
            Ws[row][col + 3] = f2tf32(pw[l].w);
        }
        __syncthreads();

        if (k0 + BK < K) {
#pragma unroll
            for (int l = 0; l < 4; l++) {
                int idx = l * 256 + tid;
                int row = idx >> 3, col = (idx & 7) * 4;
                px[l] = *(const float4*)(Xb + (size_t)row * K + k0 + BK + col);
                pw[l] = *(const float4*)(Wb + (size_t)row * K + k0 + BK + col);
            }
        }

#pragma unroll
        for (int kk = 0; kk < BK; kk += 8) {
            unsigned a[2][4];
#pragma unroll
            for (int mi = 0; mi < 2; mi++) {
                a[mi][0] = Xs[m0w + mi * 16 + g][kk + tg];
                a[mi][1] = Xs[m0w + mi * 16 + 8 + g][kk + tg];
                a[mi][2] = Xs[m0w + mi * 16 + g][kk + tg + 4];
                a[mi][3] = Xs[m0w + mi * 16 + 8 + g][kk + tg + 4];
            }
#pragma unroll
            for (int ni = 0; ni < 8; ni++) {
                unsigned b0 = Ws[n0w + ni * 8 + g][kk + tg];
                unsigned b1 = Ws[n0w + ni * 8 + g][kk + tg + 4];
#pragma unroll
                for (int mi = 0; mi < 2; mi++) {
                    asm volatile(
                        "mma.sync.aligned.m16n8k8.row.col.f32.tf32.tf32.f32 "
                        "{%0,%1,%2,%3}, {%4,%5,%6,%7}, {%8,%9}, {%0,%1,%2,%3};"
                        : "+f"(D[mi][ni][0]), "+f"(D[mi][ni][1]),
                          "+f"(D[mi][ni][2]), "+f"(D[mi][ni][3])
                        : "r"(a[mi][0]), "r"(a[mi][1]), "r"(a[mi][2]), "r"(a[mi][3]),
                          "r"(b0), "r"(b1));
                }
            }
        }
        __syncthreads();
    }

#pragma unroll
    for (int ni = 0; ni < 8; ni++) {
        int n = n0 + n0w + ni * 8 + 2 * tg;
        float bvx = bias[n], bvy = bias[n + 1];
#pragma unroll
        for (int mi = 0; mi < 2; mi++) {
            int mrow = m0 + m0w + mi * 16 + g;
            float2 o0 = make_float2(D[mi][ni][0] + bvx, D[mi][ni][1] + bvy);
            float2 o1 = make_float2(D[mi][ni][2] + bvx, D[mi][ni][3] + bvy);
            *(float2*)(out + (size_t)mrow * N + n)       = o0;
            *(float2*)(out + (size_t)(mrow + 8) * N + n) = o1;
        }
    }
}

// ============================================================================
// Persistent GRU recurrence — separated hi/lo split-bf16, 3-mma scheme.
// 128 CTAs = 32 unit-tiles (16 units -> 48 gate cols) x 4 batch-tiles (32 rows).
// 256 threads = 8 warps: (n-half) x (k-quarter). Warp tile m32 x n24 x 128 real k.
// Each u32 word = two consecutive real-k bf16 values (hi array / lo array).
// Per ki (16 real k): 4 ldmatrix.x4 + 6 ldmatrix.x2 + 18 mma, zero PRMT.
// ============================================================================
#define RBT 32
#define RUT 16
#define WP2 260                        // u32 words per row (256 + 4 pad)
#define OFF_WHI 0                      // Whi: 48*260
#define OFF_WLO (OFF_WHI + 48 * WP2)   // Wlo: 48*260
#define OFF_HHI (OFF_WLO + 48 * WP2)   // hhi: 32*260
#define OFF_HLO (OFF_HHI + 32 * WP2)   // hlo: 32*260
#define OFF_RED (OFF_HLO + 32 * WP2)   // red: 4*32*50 f32
#define RED_P   50
#define REC_SMEM_BYTES ((OFF_RED + 4 * 32 * RED_P) * 4)

__global__ __launch_bounds__(256)
void gru_rec(const float* __restrict__ xg,   // [B*T, 1536]
             const float* __restrict__ Whh,  // [1536, 512]
             const float* __restrict__ bhh,  // [1536]
             float* __restrict__ hseq,       // [B, T, 512]
             unsigned* __restrict__ hhiG,    // [B_][256]
             unsigned* __restrict__ hloG,    // [B_][256]
             unsigned* __restrict__ ctr)
{
    extern __shared__ unsigned smu[];
    unsigned* Whi = smu + OFF_WHI;
    unsigned* Wlo = smu + OFF_WLO;
    unsigned* hhi = smu + OFF_HHI;
    unsigned* hlo = smu + OFF_HLO;
    float*    red = (float*)(smu + OFF_RED);   // [4][32][RED_P]
    __shared__ float bh_s[48];

    const int tid = threadIdx.x;
    const int u0  = blockIdx.x * RUT;
    const int b0  = blockIdx.y * RBT;
    const unsigned nCTA = gridDim.x * gridDim.y;

    // ---- preamble: split-convert W_hh rows into hi/lo smem (once) ----
    for (int i = tid; i < 48 * (HID_ / 4); i += 256) {
        int row = i >> 7;            // 0..47 = g*16+u
        int c4  = i & 127;           // float4 index over real k
        int g = row >> 4, u = row & 15;
        float4 v = *(const float4*)(Whh + (size_t)(g * HID_ + u0 + u) * HID_ + c4 * 4);
        unsigned h0w, l0w, h1w, l1w, h2w, l2w, h3w, l3w;
        split2(v.x, h0w, l0w); split2(v.y, h1w, l1w);
        split2(v.z, h2w, l2w); split2(v.w, h3w, l3w);
        unsigned* dh = Whi + row * WP2 + c4 * 2;
        unsigned* dl = Wlo + row * WP2 + c4 * 2;
        dh[0] = h0w | (h1w << 16); dh[1] = h2w | (h3w << 16);
        dl[0] = l0w | (l1w << 16); dl[1] = l2w | (l3w << 16);
    }
    if (tid < 48) {
        int g = tid >> 4, u = tid & 15;
        bh_s[tid] = bhh[g * HID_ + u0 + u];
    }

    const int lane = tid & 31;
    const int wid  = tid >> 5;
    const int c    = lane & 3;       // 0..3
    const int g    = lane >> 2;      // 0..7
    const int kq   = wid >> 1;       // k-quarter 0..3
    const int nh   = wid & 1;        // n-half 0/1
    const int wb0  = kq * 64;        // word base of this quarter (64 words=128 k)

    // ldmatrix per-thread base addresses (shared space, bytes)
    const int r8  = lane & 7;
    const int sel = lane >> 3;       // 0..3
    unsigned hhi_sh = (unsigned)__cvta_generic_to_shared(hhi);
    unsigned hlo_sh = (unsigned)__cvta_generic_to_shared(hlo);
    unsigned whi_sh = (unsigned)__cvta_generic_to_shared(Whi);
    unsigned wlo_sh = (unsigned)__cvta_generic_to_shared(Wlo);
    unsigned aHiB[2], aLoB[2];
#pragma unroll
    for (int mi = 0; mi < 2; mi++) {
        unsigned off = (((mi * 16 + (sel & 1) * 8 + r8) * WP2 + (sel >> 1) * 4) << 2);
        aHiB[mi] = hhi_sh + off;
        aLoB[mi] = hlo_sh + off;
    }
    unsigned wHiB[3], wLoB[3];
#pragma unroll
    for (int nt = 0; nt < 3; nt++) {
        unsigned off = (((nh * 24 + nt * 8 + r8) * WP2 + (sel & 1) * 4) << 2);
        wHiB[nt] = whi_sh + off;
        wLoB[nt] = wlo_sh + off;
    }

    // epilogue ownership: 1 batch row, 2 adjacent units per thread
    const int ob = tid >> 3;          // batch row 0..31
    const int oj = tid & 7;           // unit pair -> units 2oj, 2oj+1

    // register-carried state
    float2 hp = make_float2(0.f, 0.f);
    float2 xr, xz, xn;
    {
        size_t xb = ((size_t)(b0 + ob) * T_) * NG_ + u0 + 2 * oj;
        xr = *(const float2*)(xg + xb);
        xz = *(const float2*)(xg + xb + 512);
        xn = *(const float2*)(xg + xb + 1024);
    }

    for (int t = 0; t < T_; t++) {
        // ---- stage h_prev hi/lo tiles [32][256] u32 into smem ----
        if (t == 0) {
            for (int i = tid; i < 32 * 64; i += 256) {
                int row = i >> 6, c4 = i & 63;
                *(uint4*)(hhi + row * WP2 + c4 * 4) = make_uint4(0, 0, 0, 0);
                *(uint4*)(hlo + row * WP2 + c4 * 4) = make_uint4(0, 0, 0, 0);
            }
        } else {
            for (int i = tid; i < 32 * 64; i += 256) {
                int row = i >> 6, c4 = i & 63;
                const unsigned* srcH = hhiG + (size_t)(b0 + row) * (HID_ / 2) + c4 * 4;
                const unsigned* srcL = hloG + (size_t)(b0 + row) * (HID_ / 2) + c4 * 4;
                unsigned dH = (unsigned)__cvta_generic_to_shared(hhi + row * WP2 + c4 * 4);
                unsigned dL = (unsigned)__cvta_generic_to_shared(hlo + row * WP2 + c4 * 4);
                asm volatile("cp.async.cg.shared.global [%0], [%1], 16;" :: "r"(dH), "l"(srcH));
                asm volatile("cp.async.cg.shared.global [%0], [%1], 16;" :: "r"(dL), "l"(srcL));
            }
            asm volatile("cp.async.commit_group;");
            asm volatile("cp.async.wait_group 0;");
        }
        __syncthreads();

        // ---- mma phase: warp = (nh, kq); m32 x n24 x 128 real k ----
        float D[2][3][4];
#pragma unroll
        for (int mi = 0; mi < 2; mi++)
#pragma unroll
            for (int nt = 0; nt < 3; nt++)
#pragma unroll
                for (int q = 0; q < 4; q++) D[mi][nt][q] = 0.f;

#pragma unroll 2
        for (int ki = 0; ki < 8; ki++) {
            unsigned koff = (unsigned)((wb0 + ki * 8) << 2);
            unsigned ahi[2][4], alo[2][4];
#pragma unroll
            for (int mi = 0; mi < 2; mi++) {
                ldmatrix_x4(ahi[mi], aHiB[mi] + koff);
                ldmatrix_x4(alo[mi], aLoB[mi] + koff);
            }
            unsigned bh[3][2], bl[3][2];
#pragma unroll
            for (int nt = 0; nt < 3; nt++) {
                ldmatrix_x2(bh[nt][0], bh[nt][1], wHiB[nt] + koff);
                ldmatrix_x2(bl[nt][0], bl[nt][1], wLoB[nt] + koff);
            }
#pragma unroll
            for (int nt = 0; nt < 3; nt++)
#pragma unroll
                for (int mi = 0; mi < 2; mi++) {
                    mma_bf16(D[mi][nt], ahi[mi], bh[nt][0], bh[nt][1]);  // hi*hi
                    mma_bf16(D[mi][nt], alo[mi], bh[nt][0], bh[nt][1]);  // lo*hi
                    mma_bf16(D[mi][nt], ahi[mi], bl[nt][0], bl[nt][1]);  // hi*lo
                }
        }

        // ---- store per-quarter partials ----
#pragma unroll
        for (int mi = 0; mi < 2; mi++)
#pragma unroll
            for (int nt = 0; nt < 3; nt++) {
                int col = nh * 24 + nt * 8 + 2 * c;
                int r0 = mi * 16 + g;
                *(float2*)&red[(kq * 32 + r0) * RED_P + col] =
                    make_float2(D[mi][nt][0], D[mi][nt][1]);
                *(float2*)&red[(kq * 32 + r0 + 8) * RED_P + col] =
                    make_float2(D[mi][nt][2], D[mi][nt][3]);
            }
        __syncthreads();

        // ---- prefetch next-step xg (overlaps epilogue + barrier) ----
        float2 nxr, nxz, nxn;
        if (t < T_ - 1) {
            size_t xb = ((size_t)(b0 + ob) * T_ + (t + 1)) * NG_ + u0 + 2 * oj;
            nxr = *(const float2*)(xg + xb);
            nxz = *(const float2*)(xg + xb + 512);
            nxn = *(const float2*)(xg + xb + 1024);
        }

        // ---- epilogue: 2 adjacent units of 1 batch row per thread ----
        {
            int u = 2 * oj;
            float2 sr = make_float2(bh_s[u],      bh_s[u + 1]);
            float2 sz = make_float2(bh_s[16 + u], bh_s[17 + u]);
            float2 sn = make_float2(bh_s[32 + u], bh_s[33 + u]);
#pragma unroll
            for (int q = 0; q < 4; q++) {
                const float* rp = red + (q * 32 + ob) * RED_P;
                float2 v;
                v = *(const float2*)(rp + u);       sr.x += v.x; sr.y += v.y;
                v = *(const float2*)(rp + 16 + u);  sz.x += v.x; sz.y += v.y;
                v = *(const float2*)(rp + 32 + u);  sn.x += v.x; sn.y += v.y;
            }
            float r0 = 1.f / (1.f + __expf(-(xr.x + sr.x)));
            float r1 = 1.f / (1.f + __expf(-(xr.y + sr.y)));
            float z0 = 1.f / (1.f + __expf(-(xz.x + sz.x)));
            float z1 = 1.f / (1.f + __expf(-(xz.y + sz.y)));
            float n0 = tanhf(xn.x + r0 * sn.x);
            float n1 = tanhf(xn.y + r1 * sn.y);
            float hv0 = (1.f - z0) * n0 + z0 * hp.x;
            float hv1 = (1.f - z1) * n1 + z1 * hp.y;
            *(float2*)(hseq + ((size_t)(b0 + ob) * T_ + t) * HID_ + u0 + u) =
                make_float2(hv0, hv1);
            unsigned h0w, l0w, h1w, l1w;
            split2(hv0, h0w, l0w);
            split2(hv1, h1w, l1w);
            size_t widx = (size_t)(b0 + ob) * (HID_ / 2) + (u0 >> 1) + oj;
            hhiG[widx] = h0w | (h1w << 16);
            hloG[widx] = l0w | (l1w << 16);
            hp = make_float2(hv0, hv1);
        }
        xr = nxr; xz = nxz; xn = nxn;
        __syncthreads();   // red/hi/lo reads complete before next step overwrites

        if (t < T_ - 1) {
            if (tid == 0) {
                __threadfence();
                atomicAdd(ctr, 1u);
                unsigned target = (unsigned)(t + 1) * nCTA;
                volatile unsigned* vc = ctr;
                while (*vc < target) { }
                __threadfence();
            }
            __syncthreads();
        }
    }
}

// ============================================================================
// Head
// ============================================================================
__global__ __launch_bounds__(64)
void out_proj(const float* __restrict__ hseq, const float* __restrict__ Wout,
              const float* __restrict__ bout, float* __restrict__ y)
{
    __shared__ float hs[HID_];
    const int b = blockIdx.x;
    const float* h = hseq + ((size_t)b * T_ + (T_ - 1)) * HID_;
    for (int i = threadIdx.x; i < HID_; i += 64) hs[i] = h[i];
    __syncthreads();

    const int o = threadIdx.x;
    float acc = bout[o];
    const float* w = Wout + (size_t)o * HID_;
#pragma unroll 4
    for (int k = 0; k < HID_; k += 4) {
        float4 wv = *(const float4*)(w + k);
        acc += hs[k] * wv.x + hs[k + 1] * wv.y + hs[k + 2] * wv.z + hs[k + 3] * wv.w;
    }
    y[b * OUT_ + o] = acc;
}

// ============================================================================
extern "C" void kernel_launch(void* const* d_in, const int* in_sizes, int n_in,
                              void* d_out, int out_size)
{
    (void)in_sizes; (void)n_in; (void)out_size;
    const float* x     = (const float*)d_in[0];
    const float* W_ih0 = (const float*)d_in[1];
    const float* W_hh0 = (const float*)d_in[2];
    const float* b_ih0 = (const float*)d_in[3];
    const float* b_hh0 = (const float*)d_in[4];
    const float* W_ih1 = (const float*)d_in[5];
    const float* W_hh1 = (const float*)d_in[6];
    const float* b_ih1 = (const float*)d_in[7];
    const float* b_hh1 = (const float*)d_in[8];
    const float* W_out = (const float*)d_in[9];
    const float* b_out = (const float*)d_in[10];
    float* y = (float*)d_out;

    float *xg, *h0, *h1;
    unsigned *ctr, *hhi, *hlo;
    cudaGetSymbolAddress((void**)&xg, g_xg);
    cudaGetSymbolAddress((void**)&h0, g_h0);
    cudaGetSymbolAddress((void**)&h1, g_h1);
    cudaGetSymbolAddress((void**)&ctr, g_ctr);
    cudaGetSymbolAddress((void**)&hhi, g_hhi);
    cudaGetSymbolAddress((void**)&hlo, g_hlo);

    cudaFuncSetAttribute(gru_rec, cudaFuncAttributeMaxDynamicSharedMemorySize,
                         REC_SMEM_BYTES);

    cudaMemsetAsync(ctr, 0, 2 * sizeof(unsigned));

    const dim3 ggrid(NG_ / BN, (B_ * T_) / BM);   // 12 x 256

    gemm_tf32<<<ggrid, 256>>>(x, W_ih0, b_ih0, xg, B_ * T_, NG_, IN_);
    gru_rec<<<dim3(HID_ / RUT, B_ / RBT), 256, REC_SMEM_BYTES>>>(
        xg, W_hh0, b_hh0, h0, hhi, hlo, ctr);

    gemm_tf32<<<ggrid, 256>>>(h0, W_ih1, b_ih1, xg, B_ * T_, NG_, HID_);
    gru_rec<<<dim3(HID_ / RUT, B_ / RBT), 256, REC_SMEM_BYTES>>>(
        xg, W_hh1, b_hh1, h1, hhi, hlo, ctr + 1);

    out_proj<<<B_, 64>>>(h1, W_out, b_out, y);
}